// round 8
// baseline (speedup 1.0000x reference)
#include <cuda_runtime.h>
#include <cuda_bf16.h>
#include <cstdint>

#define Bb 128
#define Tt 1024
#define Dd 256
#define Hh 512
#define Oo 128
#define G4H 2048

// ---------------- scratch ----------------
__device__ float g_xr[(size_t)Bb*Tt*Dd];      // 128 MB  x pre-rounded to tf32
__device__ float g_wxr[(size_t)G4H*Dd];       // 2 MB    Wx pre-rounded to tf32
__device__ float g_bxh[G4H];                  // bx+bh (exact fp32)
__device__ float g_xg[(size_t)Tt*Bb*G4H];     // 1 GB    precomputed input gates (fp32)
__device__ float g_hf[2][Bb][Hh];             // h double buffer (tf32-rounded fp32)
__device__ float g_hT[Bb*Hh];                 // final h (exact fp32)
__device__ unsigned g_bar;                    // grid barrier counter

// ---------------- PTX helpers ----------------
__device__ __forceinline__ unsigned smem_u32(const void* p) {
    return (unsigned)__cvta_generic_to_shared(p);
}
#define CPA16(dst, src) asm volatile("cp.async.cg.shared.global [%0], [%1], 16;\n" :: "r"(dst), "l"(src))
#define CPA_COMMIT()    asm volatile("cp.async.commit_group;\n")
#define CPA_WAIT(n)     asm volatile("cp.async.wait_group %0;\n" :: "n"(n))

__device__ __forceinline__ void ldm_x4(uint32_t* r, unsigned addr) {
    asm volatile("ldmatrix.sync.aligned.m8n8.x4.shared.b16 {%0,%1,%2,%3}, [%4];"
                 : "=r"(r[0]), "=r"(r[1]), "=r"(r[2]), "=r"(r[3]) : "r"(addr));
}
__device__ __forceinline__ void mma_tf32(float* c, const uint32_t* a, uint32_t b0, uint32_t b1) {
    asm volatile("mma.sync.aligned.m16n8k8.row.col.f32.tf32.tf32.f32 "
                 "{%0,%1,%2,%3}, {%4,%5,%6,%7}, {%8,%9}, {%0,%1,%2,%3};"
                 : "+f"(c[0]), "+f"(c[1]), "+f"(c[2]), "+f"(c[3])
                 : "r"(a[0]), "r"(a[1]), "r"(a[2]), "r"(a[3]), "r"(b0), "r"(b1));
}
__device__ __forceinline__ uint32_t tf32_bits(float f) {
    uint32_t u; asm("cvt.rna.tf32.f32 %0, %1;" : "=r"(u) : "f"(f)); return u;
}
__device__ __forceinline__ float tf32_round(float f) { return __uint_as_float(tf32_bits(f)); }
__device__ __forceinline__ float fsig(float x)  { return 1.f / (1.f + __expf(-x)); }
__device__ __forceinline__ float ftanh(float x) { return 2.f / (1.f + __expf(-2.f * x)) - 1.f; }

// ---------------- phase 0: tf32 pre-round + bias fuse ----------------
__global__ void k_convert(const float* __restrict__ x,  const float* __restrict__ Wx,
                          const float* __restrict__ bx, const float* __restrict__ bh) {
    int64_t i = (int64_t)blockIdx.x * blockDim.x + threadIdx.x;
    int64_t stride = (int64_t)gridDim.x * blockDim.x;
    for (int64_t j = i; j < (int64_t)Bb*Tt*Dd; j += stride) g_xr[j]  = tf32_round(x[j]);
    for (int64_t j = i; j < (int64_t)G4H*Dd;   j += stride) g_wxr[j] = tf32_round(Wx[j]);
    for (int64_t j = i; j < G4H;               j += stride) g_bxh[j] = bx[j] + bh[j];
}

// ---------------- phase 1: xg[t][b][4H] = x @ Wx^T + (bx+bh), tf32 mma ----------------
// CTA: one t (M=128 batch rows), N-tile=128 cols. K=256 in 2 sequential chunks of 128.
#define S1 132   // fp32 row stride: 33 x 16B chunks (odd -> conflict-free ldmatrix)
__global__ void __launch_bounds__(256, 1) k_xg() {
    extern __shared__ char sm[];
    float* As = (float*)sm;                        // [128][132]
    float* Bs = As + 128 * S1;                     // [128][132]
    const int tid = threadIdx.x, lane = tid & 31, wid = tid >> 5;
    const int t = blockIdx.y, nb0 = blockIdx.x * 128;
    const int warp_m = wid & 1, warp_n = wid >> 1; // 2x4 warps: M64 x N32 tiles

    float acc[4][4][4] = {};
    for (int ck = 0; ck < 2; ck++) {
        if (ck) __syncthreads();                   // protect smem before overwrite
        // A: x rows (b fixed t), K-chunk cols. 128 rows x 32 chunks = 4096 tasks.
        #pragma unroll
        for (int it = 0; it < 16; it++) {
            int task = tid + it * 256, b = task >> 5, c = task & 31;
            CPA16(smem_u32(As + b * S1 + c * 4),
                  g_xr + ((size_t)b * Tt + t) * Dd + ck * 128 + c * 4);
        }
        // B: Wx rows nb0..nb0+127, same K-chunk
        #pragma unroll
        for (int it = 0; it < 16; it++) {
            int task = tid + it * 256, n = task >> 5, c = task & 31;
            CPA16(smem_u32(Bs + n * S1 + c * 4),
                  g_wxr + (size_t)(nb0 + n) * Dd + ck * 128 + c * 4);
        }
        CPA_COMMIT(); CPA_WAIT(0);
        __syncthreads();

        #pragma unroll 4
        for (int kl = 0; kl < 16; kl++) {          // 16 k8-steps per chunk
            uint32_t a[4][4];
            #pragma unroll
            for (int mt = 0; mt < 4; mt++) {
                int r = warp_m * 64 + mt * 16 + (lane & 7) + ((lane >> 3) & 1) * 8;
                int c = kl * 8 + (lane >> 4) * 4;
                ldm_x4(a[mt], smem_u32(As + r * S1 + c));
            }
            uint32_t bfr[4][2];
            #pragma unroll
            for (int p = 0; p < 2; p++) {          // each ldm_x4 covers 2 n-tiles
                int m = lane >> 3;
                int r = warp_n * 32 + p * 16 + (m >> 1) * 8 + (lane & 7);
                int c = kl * 8 + (m & 1) * 4;
                uint32_t r4[4];
                ldm_x4(r4, smem_u32(Bs + r * S1 + c));
                bfr[p*2][0] = r4[0]; bfr[p*2][1] = r4[1];
                bfr[p*2+1][0] = r4[2]; bfr[p*2+1][1] = r4[3];
            }
            #pragma unroll
            for (int mt = 0; mt < 4; mt++)
                #pragma unroll
                for (int nt = 0; nt < 4; nt++)
                    mma_tf32(acc[mt][nt], a[mt], bfr[nt][0], bfr[nt][1]);
        }
    }
    // epilogue: add exact fp32 bias, write xg
    const int group = lane >> 2, tc = lane & 3;
    #pragma unroll
    for (int mt = 0; mt < 4; mt++) {
        #pragma unroll
        for (int nt = 0; nt < 4; nt++) {
            int col = nb0 + warp_n * 32 + nt * 8 + tc * 2;
            float b0 = g_bxh[col], b1 = g_bxh[col + 1];
            int row0 = warp_m * 64 + mt * 16 + group;
            float2 v0 = make_float2(acc[mt][nt][0] + b0, acc[mt][nt][1] + b1);
            float2 v1 = make_float2(acc[mt][nt][2] + b0, acc[mt][nt][3] + b1);
            *(float2*)&g_xg[((size_t)t * Bb + row0) * G4H + col] = v0;
            *(float2*)&g_xg[((size_t)t * Bb + row0 + 8) * G4H + col] = v1;
        }
    }
}

// ---------------- phase 2: persistent cooperative LSTM recurrence (tf32) ----------------
// 64 CTAs, each owns 8 h-cols (32 gate cols, col = j*4 + gate). c in registers.
// h (tf32-rounded fp32) broadcast via L2; K=512 staged as 4x128 chunks, 2 pipelined bufs.
#define S2 132
__global__ void __launch_bounds__(256, 1) k_rec(const float* __restrict__ Wh) {
    extern __shared__ char sm[];
    float* hb0 = (float*)sm;                       // [128][132]
    float* hb1 = hb0 + 128 * S2;                   // [128][132]
    uint4* bfrag = (uint4*)(hb1 + 128 * S2);       // Wh tf32 fragments, 64 KB
    const int tid = threadIdx.x, lane = tid & 31, wid = tid >> 5;
    const int warp_m = wid & 3, warp_n = wid >> 2; // 4x2 warps: M32 x N16 tiles
    const int g = blockIdx.x;                      // 0..63

    // Build Wh B-fragments once (tf32-rounded). Fragment (k8): thread gets
    // Wh'[k = k0+(lane&3)][n = nb+(lane>>2)], plus k0+4 partner.
    if (warp_m == 0) {
        for (int kit = 0; kit < 64; kit++) {
            uint32_t r[4];
            #pragma unroll
            for (int nt = 0; nt < 2; nt++) {
                int n = warp_n * 16 + nt * 8 + (lane >> 2);   // local col 0..31
                int jj = n >> 2, gate = n & 3;
                int grow = gate * Hh + g * 8 + jj;            // Wh global row
                int k0 = kit * 8 + (lane & 3);
                const float* wp = Wh + (size_t)grow * Hh;
                r[nt*2]   = tf32_bits(wp[k0]);
                r[nt*2+1] = tf32_bits(wp[k0 + 4]);
            }
            bfrag[(warp_n * 64 + kit) * 32 + lane] = make_uint4(r[0], r[1], r[2], r[3]);
        }
    }
    // zero h0 slice (parity 0)
    for (int i = tid; i < 1024; i += 256)
        g_hf[0][i >> 3][g * 8 + (i & 7)] = 0.f;
    __syncthreads();
    __threadfence();
    if (tid == 0) atomicAdd(&g_bar, 1u);

    const bool active = ((lane & 1) == 0);
    const int rbase = warp_m * 32 + (lane >> 2);
    float cst[2][2][2] = {};
    float xr[2][2][2][4];

    for (int t = 0; t < Tt; t++) {
        // prefetch xg (independent of h — overlaps barrier wait)
        if (active) {
            const float* xgt = g_xg + (size_t)t * Bb * G4H;
            #pragma unroll
            for (int mt = 0; mt < 2; mt++)
                #pragma unroll
                for (int h = 0; h < 2; h++) {
                    int row = rbase + mt * 16 + h * 8;
                    #pragma unroll
                    for (int nt = 0; nt < 2; nt++) {
                        int j = warp_n * 4 + nt * 2 + ((lane & 3) >> 1);
                        const float* p = xgt + (size_t)row * G4H + g * 8 + j;
                        #pragma unroll
                        for (int gate = 0; gate < 4; gate++)
                            xr[mt][nt][h][gate] = __ldcs(p + gate * Hh);
                    }
                }
        }
        // grid barrier: all 64 CTAs published h_t
        if (tid == 0) {
            unsigned target = 64u * (unsigned)(t + 1);
            while (*(volatile unsigned*)&g_bar < target) {}
        }
        __syncthreads();

        const float* hsrc = &g_hf[t & 1][0][0];
        float* bufs[2] = {hb0, hb1};
        // stage chunk0
        {
            float* bp = bufs[0];
            #pragma unroll
            for (int it = 0; it < 16; it++) {
                int task = tid + it * 256, b = task >> 5, c = task & 31;
                CPA16(smem_u32(bp + b * S2 + c * 4), hsrc + b * Hh + c * 4);
            }
            CPA_COMMIT();
        }
        float acc[2][2][4] = {};
        #pragma unroll
        for (int ck = 0; ck < 4; ck++) {
            if (ck < 3) {                          // stage chunk ck+1
                float* bp = bufs[(ck + 1) & 1];
                #pragma unroll
                for (int it = 0; it < 16; it++) {
                    int task = tid + it * 256, b = task >> 5, c = task & 31;
                    CPA16(smem_u32(bp + b * S2 + c * 4),
                          hsrc + b * Hh + (ck + 1) * 128 + c * 4);
                }
                CPA_COMMIT();
                CPA_WAIT(1);                       // chunk ck arrived
            } else {
                CPA_WAIT(0);
            }
            __syncthreads();
            const float* hb = bufs[ck & 1];
            #pragma unroll
            for (int kl = 0; kl < 16; kl++) {
                int kit = ck * 16 + kl;
                uint4 bq = bfrag[(warp_n * 64 + kit) * 32 + lane];
                uint32_t a[2][4];
                #pragma unroll
                for (int mt = 0; mt < 2; mt++) {
                    int r = warp_m * 32 + mt * 16 + (lane & 7) + ((lane >> 3) & 1) * 8;
                    int c = kl * 8 + (lane >> 4) * 4;
                    ldm_x4(a[mt], smem_u32(hb + r * S2 + c));
                }
                mma_tf32(acc[0][0], a[0], bq.x, bq.y);
                mma_tf32(acc[0][1], a[0], bq.z, bq.w);
                mma_tf32(acc[1][0], a[1], bq.x, bq.y);
                mma_tf32(acc[1][1], a[1], bq.z, bq.w);
            }
            __syncthreads();                       // all warps done with buf before restage
        }
        // epilogue: pair gates via shfl, LSTM cell update, publish h_{t+1}
        #pragma unroll
        for (int mt = 0; mt < 2; mt++) {
            #pragma unroll
            for (int nt = 0; nt < 2; nt++) {
                float c0 = acc[mt][nt][0], c1 = acc[mt][nt][1];
                float c2 = acc[mt][nt][2], c3 = acc[mt][nt][3];
                float p0 = __shfl_xor_sync(0xFFFFFFFFu, c0, 1);
                float p1 = __shfl_xor_sync(0xFFFFFFFFu, c1, 1);
                float p2 = __shfl_xor_sync(0xFFFFFFFFu, c2, 1);
                float p3 = __shfl_xor_sync(0xFFFFFFFFu, c3, 1);
                if (active) {
                    int j = warp_n * 4 + nt * 2 + ((lane & 3) >> 1);
                    #pragma unroll
                    for (int h = 0; h < 2; h++) {
                        float pi = (h ? c2 : c0) + xr[mt][nt][h][0];
                        float pf = (h ? c3 : c1) + xr[mt][nt][h][1];
                        float pg = (h ? p2 : p0) + xr[mt][nt][h][2];
                        float po = (h ? p3 : p1) + xr[mt][nt][h][3];
                        float ii = fsig(pi), ff = fsig(pf);
                        float gg = ftanh(pg), oo = fsig(po);
                        float cc = cst[mt][nt][h] * ff + ii * gg;
                        cst[mt][nt][h] = cc;
                        float hn = oo * ftanh(cc);
                        int row = rbase + mt * 16 + h * 8;
                        g_hf[(t + 1) & 1][row][g * 8 + j] = tf32_round(hn);
                        if (t == Tt - 1) g_hT[row * Hh + g * 8 + j] = hn;  // exact
                    }
                }
            }
        }
        __threadfence();
        __syncthreads();
        if (tid == 0) atomicAdd(&g_bar, 1u);
    }
    // reset barrier for deterministic graph replay
    if (g == 0 && tid == 0) {
        while (*(volatile unsigned*)&g_bar < 64u * 1025u) {}
        g_bar = 0u;
        __threadfence();
    }
}

// ---------------- phase 3: out = hT @ Wfc^T + bfc, plus hT copy ----------------
__global__ void k_fc(const float* __restrict__ Wfc, const float* __restrict__ bfc,
                     float* __restrict__ out, int out_size) {
    int gid = blockIdx.x * blockDim.x + threadIdx.x;
    int nthr = gridDim.x * blockDim.x;
    for (int i = gid; i < Bb * Hh && i < out_size; i += nthr) out[i] = g_hT[i];
    if (gid < Bb * Oo) {
        int b = gid >> 7, o = gid & 127;
        const float4* hp = (const float4*)&g_hT[b * Hh];
        const float4* wp = (const float4*)&Wfc[(size_t)o * Hh];
        float s = 0.f;
        #pragma unroll 8
        for (int k = 0; k < Hh / 4; k++) {
            float4 hv = hp[k], wv = wp[k];
            s += hv.x * wv.x + hv.y * wv.y + hv.z * wv.z + hv.w * wv.w;
        }
        int idx = Bb * Hh + gid;
        if (idx < out_size) out[idx] = s + bfc[o];
    }
}

// ---------------- launch ----------------
extern "C" void kernel_launch(void* const* d_in, const int* in_sizes, int n_in,
                              void* d_out, int out_size) {
    const float* x   = (const float*)d_in[0];
    const float* Wx  = (const float*)d_in[2];
    const float* bx  = (const float*)d_in[3];
    const float* Wh  = (const float*)d_in[4];
    const float* bh  = (const float*)d_in[5];
    const float* Wfc = (const float*)d_in[8];
    const float* bfc = (const float*)d_in[9];
    float* out = (float*)d_out;

    const int smem_xg  = 2 * 128 * S1 * 4;                   // 135,168 B
    const int smem_rec = 2 * 128 * S2 * 4 + 2 * 64 * 32 * 16; // 200,704 B
    cudaFuncSetAttribute(k_xg,  cudaFuncAttributeMaxDynamicSharedMemorySize, smem_xg);
    cudaFuncSetAttribute(k_rec, cudaFuncAttributeMaxDynamicSharedMemorySize, smem_rec);

    k_convert<<<2048, 256>>>(x, Wx, bx, bh);
    k_xg<<<dim3(16, 1024), 256, smem_xg>>>();
    k_rec<<<64, 256, smem_rec>>>(Wh);
    k_fc<<<64, 256>>>(Wfc, bfc, out, out_size);
}

// round 9
// speedup vs baseline: 1.9596x; 1.9596x over previous
#include <cuda_runtime.h>
#include <cuda_bf16.h>
#include <cstdint>

#define Bb 128
#define Tt 1024
#define Dd 256
#define Hh 512
#define Oo 128
#define G4H 2048

#define NG 4      // batch groups (independent LSTM chains)
#define RG 32     // rows per group
#define CG 32     // CTAs per group (each owns 64 gate cols = 16 h cols)

// ---------------- scratch ----------------
__device__ float g_xg[(size_t)Tt*Bb*G4H];     // 1 GB precomputed input gates (fp32)
__device__ float g_hf[2][Bb][Hh];             // h double buffer (tf32-rounded fp32)
__device__ float g_hT[Bb*Hh];                 // final h (exact fp32)
__device__ unsigned g_bar4[NG * 32];          // per-group barrier counters (128B apart)

// ---------------- PTX helpers ----------------
__device__ __forceinline__ unsigned smem_u32(const void* p) {
    return (unsigned)__cvta_generic_to_shared(p);
}
#define CPA16(dst, src) asm volatile("cp.async.cg.shared.global [%0], [%1], 16;\n" :: "r"(dst), "l"(src))
#define CPA_COMMIT()    asm volatile("cp.async.commit_group;\n")
#define CPA_WAIT(n)     asm volatile("cp.async.wait_group %0;\n" :: "n"(n))

__device__ __forceinline__ void ldm_x4(uint32_t* r, unsigned addr) {
    asm volatile("ldmatrix.sync.aligned.m8n8.x4.shared.b16 {%0,%1,%2,%3}, [%4];"
                 : "=r"(r[0]), "=r"(r[1]), "=r"(r[2]), "=r"(r[3]) : "r"(addr));
}
__device__ __forceinline__ void mma_tf32(float* c, const uint32_t* a, uint32_t b0, uint32_t b1) {
    asm volatile("mma.sync.aligned.m16n8k8.row.col.f32.tf32.tf32.f32 "
                 "{%0,%1,%2,%3}, {%4,%5,%6,%7}, {%8,%9}, {%0,%1,%2,%3};"
                 : "+f"(c[0]), "+f"(c[1]), "+f"(c[2]), "+f"(c[3])
                 : "r"(a[0]), "r"(a[1]), "r"(a[2]), "r"(a[3]), "r"(b0), "r"(b1));
}
__device__ __forceinline__ uint32_t tf32_bits(float f) {
    uint32_t u; asm("cvt.rna.tf32.f32 %0, %1;" : "=r"(u) : "f"(f)); return u;
}
__device__ __forceinline__ uint32_t tf32_rebits(uint32_t u) {
    return tf32_bits(__uint_as_float(u));
}
__device__ __forceinline__ float tf32_round(float f) { return __uint_as_float(tf32_bits(f)); }
__device__ __forceinline__ unsigned ld_acq(const unsigned* p) {
    unsigned v; asm volatile("ld.acquire.gpu.u32 %0, [%1];" : "=r"(v) : "l"(p) : "memory"); return v;
}
__device__ __forceinline__ void red_rel(unsigned* p, unsigned v) {
    asm volatile("red.release.gpu.add.u32 [%0], %1;" :: "l"(p), "r"(v) : "memory");
}
__device__ __forceinline__ float fsig(float x)  { return 1.f / (1.f + __expf(-x)); }
__device__ __forceinline__ float ftanh(float x) { return 2.f / (1.f + __expf(-2.f * x)) - 1.f; }

// ---------------- phase 1: xg[t][b][4H] = x @ Wx^T + (bx+bh), tf32 mma ----------------
// CTA: one t (M=128 batch), N-tile=128. K=256 in 4 chunks of 64. tf32 rounding in-register.
#define S1 68    // fp32 row stride: 17 x 16B chunks (odd -> conflict-free ldmatrix)
__global__ void __launch_bounds__(256, 2) k_xg(const float* __restrict__ x,
                                               const float* __restrict__ Wx,
                                               const float* __restrict__ bx,
                                               const float* __restrict__ bh) {
    extern __shared__ char sm[];
    float* As = (float*)sm;                        // [128][68]
    float* Bs = As + 128 * S1;                     // [128][68]
    const int tid = threadIdx.x, lane = tid & 31, wid = tid >> 5;
    const int t = blockIdx.y, nb0 = blockIdx.x * 128;
    const int warp_m = wid & 1, warp_n = wid >> 1; // 2x4 warps: M64 x N32 tiles

    float acc[4][4][4] = {};
    #pragma unroll 1
    for (int ck = 0; ck < 4; ck++) {
        if (ck) __syncthreads();
        // A: x rows (fixed t), 64-col K-chunk. 128 rows x 16 chunks = 2048 tasks.
        #pragma unroll
        for (int it = 0; it < 8; it++) {
            int task = tid + it * 256, b = task >> 4, c = task & 15;
            CPA16(smem_u32(As + b * S1 + c * 4),
                  x + ((size_t)b * Tt + t) * Dd + ck * 64 + c * 4);
        }
        // B: Wx rows nb0..nb0+127, same K-chunk
        #pragma unroll
        for (int it = 0; it < 8; it++) {
            int task = tid + it * 256, n = task >> 4, c = task & 15;
            CPA16(smem_u32(Bs + n * S1 + c * 4),
                  Wx + (size_t)(nb0 + n) * Dd + ck * 64 + c * 4);
        }
        CPA_COMMIT(); CPA_WAIT(0);
        __syncthreads();

        #pragma unroll
        for (int kl = 0; kl < 8; kl++) {           // 8 k8-steps per chunk
            uint32_t a[4][4];
            #pragma unroll
            for (int mt = 0; mt < 4; mt++) {
                int r = warp_m * 64 + mt * 16 + (lane & 7) + ((lane >> 3) & 1) * 8;
                int c = kl * 8 + (lane >> 4) * 4;
                ldm_x4(a[mt], smem_u32(As + r * S1 + c));
                #pragma unroll
                for (int q = 0; q < 4; q++) a[mt][q] = tf32_rebits(a[mt][q]);
            }
            uint32_t bfr[4][2];
            #pragma unroll
            for (int p = 0; p < 2; p++) {
                int m = lane >> 3;
                int r = warp_n * 32 + p * 16 + (m >> 1) * 8 + (lane & 7);
                int c = kl * 8 + (m & 1) * 4;
                uint32_t r4[4];
                ldm_x4(r4, smem_u32(Bs + r * S1 + c));
                bfr[p*2][0]   = tf32_rebits(r4[0]); bfr[p*2][1]   = tf32_rebits(r4[1]);
                bfr[p*2+1][0] = tf32_rebits(r4[2]); bfr[p*2+1][1] = tf32_rebits(r4[3]);
            }
            #pragma unroll
            for (int mt = 0; mt < 4; mt++)
                #pragma unroll
                for (int nt = 0; nt < 4; nt++)
                    mma_tf32(acc[mt][nt], a[mt], bfr[nt][0], bfr[nt][1]);
        }
    }
    // epilogue: add exact fp32 bias (bx+bh), streaming-write xg
    const int group = lane >> 2, tc = lane & 3;
    #pragma unroll
    for (int mt = 0; mt < 4; mt++) {
        #pragma unroll
        for (int nt = 0; nt < 4; nt++) {
            int col = nb0 + warp_n * 32 + nt * 8 + tc * 2;
            float b0 = __ldg(&bx[col]) + __ldg(&bh[col]);
            float b1 = __ldg(&bx[col + 1]) + __ldg(&bh[col + 1]);
            int row0 = warp_m * 64 + mt * 16 + group;
            float2 v0 = make_float2(acc[mt][nt][0] + b0, acc[mt][nt][1] + b1);
            float2 v1 = make_float2(acc[mt][nt][2] + b0, acc[mt][nt][3] + b1);
            __stcs((float2*)&g_xg[((size_t)t * Bb + row0) * G4H + col], v0);
            __stcs((float2*)&g_xg[((size_t)t * Bb + row0 + 8) * G4H + col], v1);
        }
    }
}

// ---------------- phase 2: grouped persistent LSTM recurrence (tf32) ----------------
// 4 independent groups of 32 batch rows; 32 CTAs per group (128 total, all resident).
// Each CTA owns 64 gate cols (16 h cols) for its group's rows; c-state in registers.
// Per step: group-local barrier, stage 64KB h slice (4 pipelined cp.async chunks), MMA.
#define S2 516   // fp32 row stride for h smem: 129 x 16B chunks (odd)
__global__ void __launch_bounds__(256, 1) k_rec(const float* __restrict__ Wh) {
    extern __shared__ char sm[];
    float* hb = (float*)sm;                        // [32][516]  66 KB
    uint4* bfrag = (uint4*)(hb + RG * S2);         // Wh tf32 fragments, 128 KB
    const int tid = threadIdx.x, lane = tid & 31, wid = tid >> 5;
    const int warp_m = wid & 1, warp_n = wid >> 1; // 2x4 warps: M16 x N16 tiles
    const int grp = blockIdx.x >> 5, cn = blockIdx.x & 31;
    const int colbase = cn * 16;                   // owned h cols
    const int row0 = grp * RG;                     // owned batch rows
    unsigned* bar = &g_bar4[grp * 32];

    // Build Wh B-fragments once (tf32-rounded). kit split across warp_m.
    for (int kit = warp_m * 32; kit < warp_m * 32 + 32; kit++) {
        uint32_t r[4];
        #pragma unroll
        for (int nt = 0; nt < 2; nt++) {
            int n = warp_n * 16 + nt * 8 + (lane >> 2);   // local gate col 0..63
            int jj = n >> 2, gate = n & 3;
            int grow = gate * Hh + colbase + jj;          // Wh global row
            int k0 = kit * 8 + (lane & 3);
            const float* wp = Wh + (size_t)grow * Hh;
            r[nt*2]   = tf32_bits(wp[k0]);
            r[nt*2+1] = tf32_bits(wp[k0 + 4]);
        }
        bfrag[(warp_n * 64 + kit) * 32 + lane] = make_uint4(r[0], r[1], r[2], r[3]);
    }
    // zero h0 slice (32 rows x 16 cols), publish
    for (int i = tid; i < RG * 16; i += 256)
        g_hf[0][row0 + (i >> 4)][colbase + (i & 15)] = 0.f;
    __syncthreads();
    if (tid == 0) red_rel(bar, 1u);

    const bool active = ((lane & 1) == 0);
    const int rbase = warp_m * 16 + (lane >> 2);
    float cst[2][2] = {};                          // c state [nt][rowhalf]
    float xr[2][2][4];                             // prefetched xg gates

    for (int t = 0; t < Tt; t++) {
        // prefetch xg for this step (overlaps the barrier wait)
        if (active) {
            const float* xgt = g_xg + (size_t)t * Bb * G4H;
            #pragma unroll
            for (int nt = 0; nt < 2; nt++)
                #pragma unroll
                for (int h = 0; h < 2; h++) {
                    int row = row0 + rbase + h * 8;
                    int j = warp_n * 4 + nt * 2 + ((lane & 3) >> 1);
                    const float* p = xgt + (size_t)row * G4H + colbase + j;
                    #pragma unroll
                    for (int gate = 0; gate < 4; gate++)
                        xr[nt][h][gate] = __ldcs(p + gate * Hh);
                }
        }
        // group barrier: all CG CTAs published h_t
        if (tid == 0) {
            unsigned target = (unsigned)CG * (unsigned)(t + 1);
            while (ld_acq(bar) < target) {}
        }
        __syncthreads();
        // stage group h slice (32 x 512 fp32 = 64 KB) in 4 pipelined K-chunks
        #pragma unroll
        for (int ck = 0; ck < 4; ck++) {
            #pragma unroll
            for (int it = 0; it < 4; it++) {
                int task = tid + it * 256;
                int r = task >> 5, c = (task & 31) + ck * 32;
                CPA16(smem_u32(hb + r * S2 + c * 4), &g_hf[t & 1][row0 + r][c * 4]);
            }
            CPA_COMMIT();
        }
        float acc[2][4] = {};
        #pragma unroll
        for (int ck = 0; ck < 4; ck++) {
            if (ck == 0)      CPA_WAIT(3);
            else if (ck == 1) CPA_WAIT(2);
            else if (ck == 2) CPA_WAIT(1);
            else              CPA_WAIT(0);
            __syncthreads();
            #pragma unroll
            for (int kl = 0; kl < 16; kl++) {
                int kit = ck * 16 + kl;
                uint4 bq = bfrag[(warp_n * 64 + kit) * 32 + lane];
                uint32_t a[4];
                int r = warp_m * 16 + (lane & 7) + ((lane >> 3) & 1) * 8;
                int c = kit * 8 + (lane >> 4) * 4;
                ldm_x4(a, smem_u32(hb + r * S2 + c));
                mma_tf32(acc[0], a, bq.x, bq.y);
                mma_tf32(acc[1], a, bq.z, bq.w);
            }
        }
        // epilogue: pair gates via shfl, LSTM cell update, publish h_{t+1}
        #pragma unroll
        for (int nt = 0; nt < 2; nt++) {
            float c0 = acc[nt][0], c1 = acc[nt][1];
            float c2 = acc[nt][2], c3 = acc[nt][3];
            float p0 = __shfl_xor_sync(0xFFFFFFFFu, c0, 1);
            float p1 = __shfl_xor_sync(0xFFFFFFFFu, c1, 1);
            float p2 = __shfl_xor_sync(0xFFFFFFFFu, c2, 1);
            float p3 = __shfl_xor_sync(0xFFFFFFFFu, c3, 1);
            if (active) {
                int j = warp_n * 4 + nt * 2 + ((lane & 3) >> 1);
                #pragma unroll
                for (int h = 0; h < 2; h++) {
                    float pi = (h ? c2 : c0) + xr[nt][h][0];
                    float pf = (h ? c3 : c1) + xr[nt][h][1];
                    float pg = (h ? p2 : p0) + xr[nt][h][2];
                    float po = (h ? p3 : p1) + xr[nt][h][3];
                    float ii = fsig(pi), ff = fsig(pf);
                    float gg = ftanh(pg), oo = fsig(po);
                    float cc = cst[nt][h] * ff + ii * gg;
                    cst[nt][h] = cc;
                    float hn = oo * ftanh(cc);
                    int row = row0 + rbase + h * 8;
                    g_hf[(t + 1) & 1][row][colbase + j] = tf32_round(hn);
                    if (t == Tt - 1) g_hT[row * Hh + colbase + j] = hn;  // exact
                }
            }
        }
        __syncthreads();                 // all h stores done before release
        if (tid == 0) red_rel(bar, 1u);
    }
    // reset group barrier for deterministic graph replay
    if (cn == 0 && tid == 0) {
        unsigned fin = (unsigned)CG * (unsigned)(Tt + 1);
        while (ld_acq(bar) < fin) {}
        *bar = 0u;
        __threadfence();
    }
}

// ---------------- phase 3: out = hT @ Wfc^T + bfc, plus hT copy ----------------
__global__ void k_fc(const float* __restrict__ Wfc, const float* __restrict__ bfc,
                     float* __restrict__ out, int out_size) {
    int gid = blockIdx.x * blockDim.x + threadIdx.x;
    int nthr = gridDim.x * blockDim.x;
    for (int i = gid; i < Bb * Hh && i < out_size; i += nthr) out[i] = g_hT[i];
    if (gid < Bb * Oo) {
        int b = gid >> 7, o = gid & 127;
        const float4* hp = (const float4*)&g_hT[b * Hh];
        const float4* wp = (const float4*)&Wfc[(size_t)o * Hh];
        float s = 0.f;
        #pragma unroll 8
        for (int k = 0; k < Hh / 4; k++) {
            float4 hv = hp[k], wv = wp[k];
            s += hv.x * wv.x + hv.y * wv.y + hv.z * wv.z + hv.w * wv.w;
        }
        int idx = Bb * Hh + gid;
        if (idx < out_size) out[idx] = s + bfc[o];
    }
}

// ---------------- launch ----------------
extern "C" void kernel_launch(void* const* d_in, const int* in_sizes, int n_in,
                              void* d_out, int out_size) {
    const float* x   = (const float*)d_in[0];
    const float* Wx  = (const float*)d_in[2];
    const float* bx  = (const float*)d_in[3];
    const float* Wh  = (const float*)d_in[4];
    const float* bh  = (const float*)d_in[5];
    const float* Wfc = (const float*)d_in[8];
    const float* bfc = (const float*)d_in[9];
    float* out = (float*)d_out;

    const int smem_xg  = 2 * 128 * S1 * 4;                  // 69,632 B  (2 CTAs/SM)
    const int smem_rec = RG * S2 * 4 + 4 * 64 * 32 * 16;    // 197,120 B
    cudaFuncSetAttribute(k_xg,  cudaFuncAttributeMaxDynamicSharedMemorySize, smem_xg);
    cudaFuncSetAttribute(k_rec, cudaFuncAttributeMaxDynamicSharedMemorySize, smem_rec);

    k_xg<<<dim3(16, 1024), 256, smem_xg>>>(x, Wx, bx, bh);
    k_rec<<<NG * CG, 256, smem_rec>>>(Wh);
    k_fc<<<256, 256>>>(Wfc, bfc, out, out_size);
}

// round 10
// speedup vs baseline: 2.5113x; 1.2815x over previous
#include <cuda_runtime.h>
#include <cuda_bf16.h>
#include <cstdint>

#define Bb 128
#define Tt 1024
#define Dd 256
#define Hh 512
#define Oo 128
#define G4H 2048

#define NG 4      // batch groups (independent LSTM chains)
#define RG 32     // rows per group
#define CG 32     // CTAs per group (each owns 64 gate cols = 16 h cols)

// ---------------- scratch ----------------
__device__ float g_xg[(size_t)Tt*Bb*G4H];     // 1 GB precomputed input gates (fp32)
__device__ float g_hf[2][Bb][Hh];             // h double buffer (tf32-rounded fp32)
__device__ float g_hT[Bb*Hh];                 // final h (exact fp32)
__device__ unsigned g_bar4[NG * 4 * 32];      // per-(group,chunk) flags, 128B apart

// ---------------- PTX helpers ----------------
__device__ __forceinline__ unsigned smem_u32(const void* p) {
    return (unsigned)__cvta_generic_to_shared(p);
}
#define CPA16(dst, src) asm volatile("cp.async.cg.shared.global [%0], [%1], 16;\n" :: "r"(dst), "l"(src))
#define CPA_COMMIT()    asm volatile("cp.async.commit_group;\n")
#define CPA_WAIT(n)     asm volatile("cp.async.wait_group %0;\n" :: "n"(n))

__device__ __forceinline__ void ldm_x4(uint32_t* r, unsigned addr) {
    asm volatile("ldmatrix.sync.aligned.m8n8.x4.shared.b16 {%0,%1,%2,%3}, [%4];"
                 : "=r"(r[0]), "=r"(r[1]), "=r"(r[2]), "=r"(r[3]) : "r"(addr));
}
__device__ __forceinline__ void mma_tf32(float* c, const uint32_t* a, uint32_t b0, uint32_t b1) {
    asm volatile("mma.sync.aligned.m16n8k8.row.col.f32.tf32.tf32.f32 "
                 "{%0,%1,%2,%3}, {%4,%5,%6,%7}, {%8,%9}, {%0,%1,%2,%3};"
                 : "+f"(c[0]), "+f"(c[1]), "+f"(c[2]), "+f"(c[3])
                 : "r"(a[0]), "r"(a[1]), "r"(a[2]), "r"(a[3]), "r"(b0), "r"(b1));
}
__device__ __forceinline__ uint32_t tf32_bits(float f) {
    uint32_t u; asm("cvt.rna.tf32.f32 %0, %1;" : "=r"(u) : "f"(f)); return u;
}
__device__ __forceinline__ uint32_t tf32_rebits(uint32_t u) {
    return tf32_bits(__uint_as_float(u));
}
__device__ __forceinline__ float tf32_round(float f) { return __uint_as_float(tf32_bits(f)); }
__device__ __forceinline__ unsigned ld_acq(const unsigned* p) {
    unsigned v; asm volatile("ld.acquire.gpu.u32 %0, [%1];" : "=r"(v) : "l"(p) : "memory"); return v;
}
__device__ __forceinline__ void red_rel(unsigned* p, unsigned v) {
    asm volatile("red.release.gpu.add.u32 [%0], %1;" :: "l"(p), "r"(v) : "memory");
}
__device__ __forceinline__ float fsig(float x)  { return 1.f / (1.f + __expf(-x)); }
__device__ __forceinline__ float ftanh(float x) { return 2.f / (1.f + __expf(-2.f * x)) - 1.f; }

// ---------------- phase 1: xg[t][b][4H] = x @ Wx^T + (bx+bh), tf32 mma ----------------
// (unchanged from R8 — verified passing)
#define S1 68    // fp32 row stride: 17 x 16B chunks (odd -> conflict-free ldmatrix)
__global__ void __launch_bounds__(256, 2) k_xg(const float* __restrict__ x,
                                               const float* __restrict__ Wx,
                                               const float* __restrict__ bx,
                                               const float* __restrict__ bh) {
    extern __shared__ char sm[];
    float* As = (float*)sm;                        // [128][68]
    float* Bs = As + 128 * S1;                     // [128][68]
    const int tid = threadIdx.x, lane = tid & 31, wid = tid >> 5;
    const int t = blockIdx.y, nb0 = blockIdx.x * 128;
    const int warp_m = wid & 1, warp_n = wid >> 1; // 2x4 warps: M64 x N32 tiles

    float acc[4][4][4] = {};
    #pragma unroll 1
    for (int ck = 0; ck < 4; ck++) {
        if (ck) __syncthreads();
        #pragma unroll
        for (int it = 0; it < 8; it++) {
            int task = tid + it * 256, b = task >> 4, c = task & 15;
            CPA16(smem_u32(As + b * S1 + c * 4),
                  x + ((size_t)b * Tt + t) * Dd + ck * 64 + c * 4);
        }
        #pragma unroll
        for (int it = 0; it < 8; it++) {
            int task = tid + it * 256, n = task >> 4, c = task & 15;
            CPA16(smem_u32(Bs + n * S1 + c * 4),
                  Wx + (size_t)(nb0 + n) * Dd + ck * 64 + c * 4);
        }
        CPA_COMMIT(); CPA_WAIT(0);
        __syncthreads();

        #pragma unroll
        for (int kl = 0; kl < 8; kl++) {
            uint32_t a[4][4];
            #pragma unroll
            for (int mt = 0; mt < 4; mt++) {
                int r = warp_m * 64 + mt * 16 + (lane & 7) + ((lane >> 3) & 1) * 8;
                int c = kl * 8 + (lane >> 4) * 4;
                ldm_x4(a[mt], smem_u32(As + r * S1 + c));
                #pragma unroll
                for (int q = 0; q < 4; q++) a[mt][q] = tf32_rebits(a[mt][q]);
            }
            uint32_t bfr[4][2];
            #pragma unroll
            for (int p = 0; p < 2; p++) {
                int m = lane >> 3;
                int r = warp_n * 32 + p * 16 + (m >> 1) * 8 + (lane & 7);
                int c = kl * 8 + (m & 1) * 4;
                uint32_t r4[4];
                ldm_x4(r4, smem_u32(Bs + r * S1 + c));
                bfr[p*2][0]   = tf32_rebits(r4[0]); bfr[p*2][1]   = tf32_rebits(r4[1]);
                bfr[p*2+1][0] = tf32_rebits(r4[2]); bfr[p*2+1][1] = tf32_rebits(r4[3]);
            }
            #pragma unroll
            for (int mt = 0; mt < 4; mt++)
                #pragma unroll
                for (int nt = 0; nt < 4; nt++)
                    mma_tf32(acc[mt][nt], a[mt], bfr[nt][0], bfr[nt][1]);
        }
    }
    const int group = lane >> 2, tc = lane & 3;
    #pragma unroll
    for (int mt = 0; mt < 4; mt++) {
        #pragma unroll
        for (int nt = 0; nt < 4; nt++) {
            int col = nb0 + warp_n * 32 + nt * 8 + tc * 2;
            float b0 = __ldg(&bx[col]) + __ldg(&bh[col]);
            float b1 = __ldg(&bx[col + 1]) + __ldg(&bh[col + 1]);
            int row0 = warp_m * 64 + mt * 16 + group;
            float2 v0 = make_float2(acc[mt][nt][0] + b0, acc[mt][nt][1] + b1);
            float2 v1 = make_float2(acc[mt][nt][2] + b0, acc[mt][nt][3] + b1);
            __stcs((float2*)&g_xg[((size_t)t * Bb + row0) * G4H + col], v0);
            __stcs((float2*)&g_xg[((size_t)t * Bb + row0 + 8) * G4H + col], v1);
        }
    }
}

// ---------------- phase 2: grouped LSTM recurrence, chunk-dataflow version ----------------
// 4 groups x 32 CTAs. CTA: M=32 rows, N=64 gate cols, K=512.
// 8 warps = 4 K-chunks x 2 N-halves (M32xN32xK128 per warp). Wh read once from smem
// (last 4 k-iters per warp in registers). Producers signal per-K-chunk flags; each
// k-warp spins only on its chunk, stages it, MMAs. K-partials reduced via smem.
#define S2 516   // fp32 row stride for h smem: 129 x 16B chunks (odd)
#define PB 72    // pbuf padded row stride (72 % 32 == 8 -> conflict-free STS.64)
__global__ void __launch_bounds__(256, 1) k_rec(const float* __restrict__ Wh) {
    extern __shared__ char sm[];
    float* hb   = (float*)sm;                      // [32][516]      66048 B
    float* pbuf = hb + RG * S2;                    // [4][32][72]    36864 B
    char*  bfr  = (char*)(pbuf + 4 * 32 * PB);     // 8 x 12288 B =  98304 B
    const int tid = threadIdx.x, lane = tid & 31, wid = tid >> 5;
    const int kc = wid >> 1, tau = wid & 1;        // K-chunk, N-half of this warp
    const int grp = blockIdx.x >> 5, cn = blockIdx.x & 31;
    const int colbase = cn * 16, row0 = grp * RG;
    unsigned* flags  = &g_bar4[grp * 4 * 32];
    unsigned* myflag = &flags[(cn >> 3) * 32];     // chunk this CTA's h slice feeds
    unsigned* kflag  = &flags[kc * 32];            // chunk this warp consumes

    // Build Wh B-fragments once (tf32-rounded); per warp its (kc, tau) slice.
    // kl 0..11 -> smem, kl 12..15 -> registers.
    uint4 breg[8];
    char* wb = bfr + wid * 12288;
    for (int kl = 0; kl < 16; kl++) {
        #pragma unroll
        for (int h2 = 0; h2 < 2; h2++) {
            uint32_t v[4];
            #pragma unroll
            for (int q = 0; q < 2; q++) {
                int nt = h2 * 2 + q;
                int n = tau * 32 + nt * 8 + (lane >> 2);  // local gate col 0..63
                int jj = n >> 2, gate = n & 3;
                int grow = gate * Hh + colbase + jj;      // Wh global row
                int k = kc * 128 + kl * 8 + (lane & 3);
                const float* wp = Wh + (size_t)grow * Hh;
                v[q*2]   = tf32_bits(wp[k]);
                v[q*2+1] = tf32_bits(wp[k + 4]);
            }
            uint4 u = make_uint4(v[0], v[1], v[2], v[3]);
            if (kl < 12) *(uint4*)(wb + (kl * 2 + h2) * 512 + lane * 16) = u;
            else breg[(kl - 12) * 2 + h2] = u;
        }
    }
    // zero h0 slice (task mapping), publish chunk readiness
    for (int tk = tid; tk < 512; tk += 256)
        g_hf[0][row0 + (tk >> 4)][colbase + (tk & 15)] = 0.f;
    __syncthreads();
    if (tid == 0) red_rel(myflag, 1u);

    float cst[2] = {0.f, 0.f};                     // c-state per epilogue task

    for (int t = 0; t < Tt; t++) {
        // xg prefetch for this thread's epilogue tasks (overlaps spin)
        float xr[2][4];
        {
            const float* xgt = g_xg + (size_t)t * Bb * G4H;
            #pragma unroll
            for (int s = 0; s < 2; s++) {
                int tk = tid + s * 256;
                int row = row0 + (tk >> 4), j = colbase + (tk & 15);
                const float* p = xgt + (size_t)row * G4H + j;
                #pragma unroll
                for (int gt = 0; gt < 4; gt++) xr[s][gt] = __ldcs(p + gt * Hh);
            }
        }
        // per-warp spin: only this warp's K-chunk producers (8 CTAs)
        if (lane == 0) {
            unsigned tgt = 8u * (unsigned)(t + 1);
            while (ld_acq(kflag) < tgt) {}
        }
        __syncwarp();
        // stage this warp's half of chunk kc (8 KB); partner-sync via named barrier
        {
            const float* hsrc = &g_hf[t & 1][row0][0];
            #pragma unroll
            for (int i = 0; i < 16; i++) {
                int row = i * 2 + (lane >> 4);
                int cw = kc * 128 + (tau * 16 + (lane & 15)) * 4;
                CPA16(smem_u32(hb + row * S2 + cw), hsrc + (size_t)row * Hh + cw);
            }
            CPA_COMMIT(); CPA_WAIT(0);
            asm volatile("bar.sync %0, 64;" :: "r"(1 + kc) : "memory");
        }
        // MMA: M32 x N32(tau) x K128(kc)
        float acc[2][4][4] = {};
        #pragma unroll
        for (int kl = 0; kl < 16; kl++) {
            uint4 q0, q1;
            if (kl < 12) {
                q0 = *(const uint4*)(wb + (kl * 2 + 0) * 512 + lane * 16);
                q1 = *(const uint4*)(wb + (kl * 2 + 1) * 512 + lane * 16);
            } else {
                q0 = breg[(kl - 12) * 2];
                q1 = breg[(kl - 12) * 2 + 1];
            }
            uint32_t a0[4], a1[4];
            int c = kc * 128 + kl * 8 + (lane >> 4) * 4;
            int rr = (lane & 7) + ((lane >> 3) & 1) * 8;
            ldm_x4(a0, smem_u32(hb + rr * S2 + c));
            ldm_x4(a1, smem_u32(hb + (rr + 16) * S2 + c));
            mma_tf32(acc[0][0], a0, q0.x, q0.y);
            mma_tf32(acc[0][1], a0, q0.z, q0.w);
            mma_tf32(acc[0][2], a0, q1.x, q1.y);
            mma_tf32(acc[0][3], a0, q1.z, q1.w);
            mma_tf32(acc[1][0], a1, q0.x, q0.y);
            mma_tf32(acc[1][1], a1, q0.z, q0.w);
            mma_tf32(acc[1][2], a1, q1.x, q1.y);
            mma_tf32(acc[1][3], a1, q1.z, q1.w);
        }
        // store K-partials in logical (row, gatecol) layout
        #pragma unroll
        for (int mt = 0; mt < 2; mt++) {
            #pragma unroll
            for (int nt = 0; nt < 4; nt++) {
                int r = mt * 16 + (lane >> 2);
                int n = tau * 32 + nt * 8 + (lane & 3) * 2;
                *(float2*)&pbuf[(kc * 32 + r) * PB + n] =
                    make_float2(acc[mt][nt][0], acc[mt][nt][1]);
                *(float2*)&pbuf[(kc * 32 + r + 8) * PB + n] =
                    make_float2(acc[mt][nt][2], acc[mt][nt][3]);
            }
        }
        __syncthreads();
        // reduce 4 K-partials + LSTM cell update per task, publish h_{t+1}
        #pragma unroll
        for (int s = 0; s < 2; s++) {
            int tk = tid + s * 256;
            int row = tk >> 4, j = tk & 15;
            float4 sum = *(float4*)&pbuf[row * PB + j * 4];
            #pragma unroll
            for (int k = 1; k < 4; k++) {
                float4 p = *(float4*)&pbuf[(k * 32 + row) * PB + j * 4];
                sum.x += p.x; sum.y += p.y; sum.z += p.z; sum.w += p.w;
            }
            float pi = sum.x + xr[s][0];
            float pf = sum.y + xr[s][1];
            float pg = sum.z + xr[s][2];
            float po = sum.w + xr[s][3];
            float ii = fsig(pi), ff = fsig(pf), gg = ftanh(pg), oo = fsig(po);
            float cc = cst[s] * ff + ii * gg;
            cst[s] = cc;
            float hn = oo * ftanh(cc);
            g_hf[(t + 1) & 1][row0 + row][colbase + j] = tf32_round(hn);
            if (t == Tt - 1) g_hT[(row0 + row) * Hh + colbase + j] = hn;  // exact
        }
        __syncthreads();                 // all publishes done before release
        if (tid == 0) red_rel(myflag, 1u);
    }
    // reset group flags for deterministic graph replay
    if (cn == 0 && tid == 0) {
        unsigned fin = 8u * (unsigned)(Tt + 1);
        for (int ch = 0; ch < 4; ch++) {
            while (ld_acq(&flags[ch * 32]) < fin) {}
            *(volatile unsigned*)&flags[ch * 32] = 0u;
        }
        __threadfence();
    }
}

// ---------------- phase 3: out = hT @ Wfc^T + bfc, plus hT copy ----------------
__global__ void k_fc(const float* __restrict__ Wfc, const float* __restrict__ bfc,
                     float* __restrict__ out, int out_size) {
    int gid = blockIdx.x * blockDim.x + threadIdx.x;
    int nthr = gridDim.x * blockDim.x;
    for (int i = gid; i < Bb * Hh && i < out_size; i += nthr) out[i] = g_hT[i];
    if (gid < Bb * Oo) {
        int b = gid >> 7, o = gid & 127;
        const float4* hp = (const float4*)&g_hT[b * Hh];
        const float4* wp = (const float4*)&Wfc[(size_t)o * Hh];
        float s = 0.f;
        #pragma unroll 8
        for (int k = 0; k < Hh / 4; k++) {
            float4 hv = hp[k], wv = wp[k];
            s += hv.x * wv.x + hv.y * wv.y + hv.z * wv.z + hv.w * wv.w;
        }
        int idx = Bb * Hh + gid;
        if (idx < out_size) out[idx] = s + bfc[o];
    }
}

// ---------------- launch ----------------
extern "C" void kernel_launch(void* const* d_in, const int* in_sizes, int n_in,
                              void* d_out, int out_size) {
    const float* x   = (const float*)d_in[0];
    const float* Wx  = (const float*)d_in[2];
    const float* bx  = (const float*)d_in[3];
    const float* Wh  = (const float*)d_in[4];
    const float* bh  = (const float*)d_in[5];
    const float* Wfc = (const float*)d_in[8];
    const float* bfc = (const float*)d_in[9];
    float* out = (float*)d_out;

    const int smem_xg  = 2 * 128 * S1 * 4;                       // 69,632 B
    const int smem_rec = RG * S2 * 4 + 4 * 32 * PB * 4 + 8 * 12288; // 201,216 B
    cudaFuncSetAttribute(k_xg,  cudaFuncAttributeMaxDynamicSharedMemorySize, smem_xg);
    cudaFuncSetAttribute(k_rec, cudaFuncAttributeMaxDynamicSharedMemorySize, smem_rec);

    k_xg<<<dim3(16, 1024), 256, smem_xg>>>(x, Wx, bx, bh);
    k_rec<<<NG * CG, 256, smem_rec>>>(Wh);
    k_fc<<<256, 256>>>(Wfc, bfc, out, out_size);
}